// round 10
// baseline (speedup 1.0000x reference)
#include <cuda_runtime.h>

// diag(ics_mask - params * r_mask) for N=12288 -> [N, N] fp32 output.
// Pure store-bandwidth problem: 604 MB of output, ~144 KB of input.
// One float4 (STG.128) per thread; diagonal element folded into the
// zero-fill via a compile-time-constant division (magic multiply).
// Streaming store hint (__stcs): output is write-once, zero-reuse, 5x L2.

static constexpr int N = 12288;
static constexpr int NP1 = N + 1;                       // 12289
static constexpr unsigned int TOTAL = (unsigned int)N * (unsigned int)N;  // 150,994,944 < 2^31
static constexpr unsigned int NVEC = TOTAL / 4;         // 37,748,736 float4s
static constexpr int TPB = 256;
static constexpr unsigned int NBLK = NVEC / TPB;        // 147,456 (exact)

__global__ __launch_bounds__(TPB) void diag_fill_kernel(
    const float* __restrict__ params,
    const int* __restrict__ r_mask,
    const int* __restrict__ ics_mask,
    float4* __restrict__ out)
{
    unsigned int v = blockIdx.x * (unsigned int)TPB + threadIdx.x;
    // Grid covers NVEC exactly; no bounds check needed.

    float4 z = make_float4(0.0f, 0.0f, 0.0f, 0.0f);

    // Linear element range covered by this thread: [e, e+4)
    unsigned int e = v * 4u;

    // Unique diagonal index i with i*(N+1) in [e, e+4), if any:
    // i = ceil(e / (N+1)); constant divisor -> IMAD magic multiply, no IDIV.
    unsigned int i = (e + (unsigned int)N) / (unsigned int)NP1;
    if (i < (unsigned int)N) {
        unsigned int p = i * (unsigned int)NP1;
        if (p < e + 4u) {
            float dv = (float)ics_mask[i] - params[i] * (float)r_mask[i];
            ((float*)&z)[p - e] = dv;
        }
    }

    __stcs(&out[v], z);   // evict-first streaming store
}

extern "C" void kernel_launch(void* const* d_in, const int* in_sizes, int n_in,
                              void* d_out, int out_size)
{
    const float* params   = (const float*)d_in[0];
    const int*   r_mask   = (const int*)d_in[1];
    const int*   ics_mask = (const int*)d_in[2];
    float4*      out      = (float4*)d_out;

    diag_fill_kernel<<<NBLK, TPB>>>(params, r_mask, ics_mask, out);
}